// round 7
// baseline (speedup 1.0000x reference)
#include <cuda_runtime.h>
#include <cuda_bf16.h>
#include <math.h>

#define H_DIM 1000
#define W_DIM 1000
#define NVERT 20
#define PX 8
#define BLOCK 128                  // one row per block, 4 warps
#define GRID  H_DIM

__global__ void __launch_bounds__(128)
render_kernel(const float* __restrict__ vpos,
              const float* __restrict__ vcol,
              const float* __restrict__ vrad,
              const float* __restrict__ cpos,
              const float* __restrict__ crot,
              const float* __restrict__ fl,
              const float* __restrict__ bg,
              float* __restrict__ out)
{
    const int tid  = threadIdx.x;
    const int lane = tid & 31;
    const int row  = blockIdx.x;
    const float gy = 1.0f - (2.0f * row + 1.0f) * (1.0f / H_DIM);

    // ---- per-warp register prepass (no smem, no block barrier) ----
    const int vi = (lane < NVERT) ? lane : 0;
    float px_ = vpos[3*vi+0], py_ = vpos[3*vi+1], pz_ = vpos[3*vi+2];
    float x = fmaf(px_, crot[0], fmaf(py_, crot[3], fmaf(pz_, crot[6], cpos[0])));
    float y = fmaf(px_, crot[1], fmaf(py_, crot[4], fmaf(pz_, crot[7], cpos[1])));
    float z = fmaf(px_, crot[2], fmaf(py_, crot[5], fmaf(pz_, crot[8], cpos[2])));
    float f    = fl[0];
    float invz = __fdividef(1.0f, z);
    float xn = f * x * invz;
    float yn = f * y * invz;
    float rn = f * vrad[vi] * invz;
    float r2v = rn * rn;
    bool in_depth = (z > 1.0f) && (z < 45.0f);
    float closeness = fminf(fmaxf((45.0f - z) * (1.0f / 44.0f), 0.0f), 1.0f);
    float Ev  = in_depth ? __expf(closeness * 10.0f) : 0.0f;   // bg logit 0 -> e^0 = 1
    float Ecr = Ev * vcol[3*vi+0];
    float Ecg = Ev * vcol[3*vi+1];
    float Ecb = Ev * vcol[3*vi+2];

    float dyv = gy - yn;
    bool cover = (lane < NVERT) && (Ev > 0.0f) && (dyv * dyv <= r2v);
    unsigned mask = __ballot_sync(0xffffffffu, cover);

    // ---- per-pixel accumulation: 8 px/thread ----
    const float dgx = -2.0f / W_DIM;
    const int   x0  = tid * PX;
    const float gx0 = 1.0f - (2.0f * x0 + 1.0f) * (1.0f / W_DIM);

    const float bgr = bg[0], bgg = bg[1], bgb = bg[2];
    float s[PX], cr[PX], cg[PX], cb[PX];
#pragma unroll
    for (int j = 0; j < PX; j++) { s[j] = 1.0f; cr[j] = bgr; cg[j] = bgg; cb[j] = bgb; }

    while (mask) {
        int i = __ffs(mask) - 1;
        mask &= mask - 1;
        float axn = __shfl_sync(0xffffffffu, xn,  i);
        float ayn = __shfl_sync(0xffffffffu, yn,  i);
        float ar2 = __shfl_sync(0xffffffffu, r2v, i);
        float aE  = __shfl_sync(0xffffffffu, Ev,  i);
        float acr = __shfl_sync(0xffffffffu, Ecr, i);
        float acg = __shfl_sync(0xffffffffu, Ecg, i);
        float acb = __shfl_sync(0xffffffffu, Ecb, i);

        float dy  = gy - ayn;
        float dy2 = dy * dy;
        float dx  = gx0 - axn;
#pragma unroll
        for (int j = 0; j < PX; j++) {
            float d = fmaf(dx, dx, dy2);
            if (d <= ar2) { s[j] += aE; cr[j] += acr; cg[j] += acg; cb[j] += acb; }
            dx += dgx;
        }
    }

    if (tid < 125) {                       // 125 threads * 8 px = 1000 px
        float o[PX * 3];
#pragma unroll
        for (int j = 0; j < PX; j++) {
            float inv = __fdividef(1.0f, s[j]);
            o[3*j+0] = cr[j] * inv;
            o[3*j+1] = cg[j] * inv;
            o[3*j+2] = cb[j] * inv;
        }
        float4* out4 = reinterpret_cast<float4*>(out) + (size_t)row * 750 + tid * 6;
#pragma unroll
        for (int k = 0; k < 6; k++)
            out4[k] = make_float4(o[4*k+0], o[4*k+1], o[4*k+2], o[4*k+3]);
    }
}

extern "C" void kernel_launch(void* const* d_in, const int* in_sizes, int n_in,
                              void* d_out, int out_size)
{
    const float* vert_pos = (const float*)d_in[0];
    const float* vert_col = (const float*)d_in[1];
    const float* vert_rad = (const float*)d_in[2];
    const float* cam_pos  = (const float*)d_in[3];
    const float* cam_rot  = (const float*)d_in[4];
    const float* focal    = (const float*)d_in[5];
    const float* bg_col   = (const float*)d_in[6];
    float* out = (float*)d_out;

    render_kernel<<<GRID, BLOCK>>>(vert_pos, vert_col, vert_rad,
                                   cam_pos, cam_rot, focal, bg_col, out);
}